// round 8
// baseline (speedup 1.0000x reference)
#include <cuda_runtime.h>
#include <cstdint>

// PatchEmbedding, 3-kernel plan:
//   1) round_w:  W [768,672] -> tf32-rounded copy Wr (2 MB)
//   2) im2col:   x gather -> tf32-rounded A matrix Ar [37440,672] (100 MB)
//   3) gemm:     D = Ar * Wr^T + bias, cp.async 3-stage, mma.m16n8k8.tf32,
//                4 warps/CTA with 64x64 warp tiles (low-redundancy fragments).

namespace {

constexpr int C_   = 4;
constexpr int Himg = 420;
constexpr int Wimg = 312;
constexpr int PH   = 14;
constexpr int PW   = 12;
constexpr int GW   = 26;
constexpr int E    = 768;
constexpr int NV   = 390;
constexpr int K    = 672;
constexpr int M    = 96 * NV;        // 37440
constexpr int HW_  = Himg * Wimg;
constexpr int CHW  = C_ * HW_;

constexpr int BM = 128, BN = 128, BK = 32;
constexpr int NKT    = K / BK;             // 21
constexpr int NBLK   = E / BN;             // 6
constexpr int MBLK   = (M + BM - 1) / BM;  // 293
constexpr int STAGES = 3;
constexpr int STAGE_BYTES = (BM + BN) * BK * 4;       // 32 KB
constexpr int SM_TOTAL    = STAGES * STAGE_BYTES;      // 96 KB

} // namespace

// scratch (module-scope device globals; allocation-free at launch time)
__device__ float g_Ar[(size_t)M * K];   // ~100.6 MB, im2col'd + tf32-rounded
__device__ float g_Wr[(size_t)E * K];   // ~2 MB, tf32-rounded

namespace {

__device__ __forceinline__ uint32_t smem_u32(const void* p) {
    uint32_t a;
    asm("{ .reg .u64 t; cvta.to.shared.u64 t, %1; cvt.u32.u64 %0, t; }"
        : "=r"(a) : "l"(p));
    return a;
}

__device__ __forceinline__ uint32_t f2tf32(float v) {
    uint32_t r;
    asm("cvt.rna.tf32.f32 %0, %1;" : "=r"(r) : "f"(v));
    return r;
}

__device__ __forceinline__ void cp16(uint32_t dst, const float* src) {
    asm volatile("cp.async.cg.shared.global [%0], [%1], 16;"
                 :: "r"(dst), "l"(src) : "memory");
}

__device__ __forceinline__ void ldsm_x4(uint32_t r[4], uint32_t addr) {
    asm volatile("ldmatrix.sync.aligned.m8n8.x4.shared.b16 {%0,%1,%2,%3}, [%4];"
                 : "=r"(r[0]), "=r"(r[1]), "=r"(r[2]), "=r"(r[3]) : "r"(addr));
}

__device__ __forceinline__ void mma_tf32(float d[4], const uint32_t a[4],
                                         uint32_t b0, uint32_t b1) {
    asm volatile(
        "mma.sync.aligned.m16n8k8.row.col.f32.tf32.tf32.f32 "
        "{%0,%1,%2,%3}, {%4,%5,%6,%7}, {%8,%9}, {%0,%1,%2,%3};"
        : "+f"(d[0]), "+f"(d[1]), "+f"(d[2]), "+f"(d[3])
        : "r"(a[0]), "r"(a[1]), "r"(a[2]), "r"(a[3]), "r"(b0), "r"(b1));
}

// ---- pre-pass 1: round W to tf32 ----
__global__ void round_w(const float* __restrict__ Wm) {
    int i = blockIdx.x * blockDim.x + threadIdx.x;   // float4 index
    constexpr int N4 = E * K / 4;
    if (i < N4) {
        float4 v = reinterpret_cast<const float4*>(Wm)[i];
        v.x = __uint_as_float(f2tf32(v.x));
        v.y = __uint_as_float(f2tf32(v.y));
        v.z = __uint_as_float(f2tf32(v.z));
        v.w = __uint_as_float(f2tf32(v.w));
        reinterpret_cast<float4*>(g_Wr)[i] = v;
    }
}

// ---- pre-pass 2: im2col gather + tf32 round. one block per output row ----
__global__ __launch_bounds__(256)
void im2col(const float* __restrict__ x, const int* __restrict__ valid) {
    const int m = blockIdx.x;
    const int n = m / NV;
    const int v = m - n * NV;
    const int p = valid[v];
    const int gi = p / GW;
    const int gj = p - gi * GW;
    const int base = n * CHW + gi * (PH * Wimg) + gj * PW;

    for (int k = threadIdx.x; k < K; k += 256) {
        int c   = k / (PH * PW);
        int rem = k - c * (PH * PW);
        int r   = rem / PW;
        int q   = rem - r * PW;
        float val = __ldg(x + base + c * HW_ + r * Wimg + q);
        g_Ar[(size_t)m * K + k] = __uint_as_float(f2tf32(val));
    }
}

// ---- main GEMM: 128 threads, 4 warps, 64x64 warp tiles ----
__global__ __launch_bounds__(128)
void patch_embed_gemm(const float* __restrict__ bias,
                      float*       __restrict__ out)
{
    extern __shared__ char smem[];
    const uint32_t sb = smem_u32(smem);

    const int tid  = threadIdx.x;
    const int lane = tid & 31;
    const int wid  = tid >> 5;

    const int bid = blockIdx.x;
    const int n0  = (bid % NBLK) * BN;   // n innermost -> A panel L2 reuse
    const int m0  = (bid / NBLK) * BM;

    // ---- cp.async: thread tid loads full 128B row tid of A and of B ----
    const int      row  = tid;                    // 0..127
    const uint32_t xm   = (row << 4) & 0x70;      // per-row swizzle mask
    const int      arow = (m0 + row < M) ? (m0 + row) : (M - 1);
    const float*   asrc = g_Ar + (size_t)arow * K;
    const float*   bsrc = g_Wr + (size_t)(n0 + row) * K;

    auto issue = [&](int kt) {
        const uint32_t ab = sb + (kt % STAGES) * STAGE_BYTES + row * 128;
        const uint32_t bb = ab + BM * BK * 4;
        const float* as = asrc + kt * BK;
        const float* bs = bsrc + kt * BK;
        #pragma unroll
        for (int j = 0; j < 8; ++j) {
            uint32_t off = (uint32_t)(j * 16) ^ xm;
            cp16(ab + off, as + j * 4);
            cp16(bb + off, bs + j * 4);
        }
    };

    // ---- fragment assignment: 2(M) x 2(N) warps, warp tile 64x64 ----
    const int wm = (wid & 1) * 64;
    const int wn = (wid >> 1) * 64;
    const int arow_l = lane & 15;
    const int aq_l   = lane >> 4;                        // A quad sel
    const int brow_l = (lane & 7) + ((lane >> 4) << 3);  // B ldmatrix row
    const int bq_l   = (lane >> 3) & 1;                  // B quad sel

    float d[4][8][4];
    #pragma unroll
    for (int i = 0; i < 4; ++i)
        #pragma unroll
        for (int j = 0; j < 8; ++j)
            #pragma unroll
            for (int r = 0; r < 4; ++r)
                d[i][j][r] = 0.0f;

    // prologue: stages 0, 1 in flight
    issue(0);
    asm volatile("cp.async.commit_group;" ::: "memory");
    issue(1);
    asm volatile("cp.async.commit_group;" ::: "memory");

    for (int kt = 0; kt < NKT; ++kt) {
        asm volatile("cp.async.wait_group 1;" ::: "memory");
        __syncthreads();                  // stage kt visible; buf (kt+2)%3 free

        if (kt + 2 < NKT) issue(kt + 2);
        asm volatile("cp.async.commit_group;" ::: "memory");

        const uint32_t abase = sb + (kt % STAGES) * STAGE_BYTES;
        const uint32_t bbase = abase + BM * BK * 4;

        #pragma unroll
        for (int s = 0; s < 4; ++s) {
            uint32_t a[4][4];
            uint32_t b[4][4];
            #pragma unroll
            for (int i = 0; i < 4; ++i) {
                int r = wm + i * 16 + arow_l;
                uint32_t off = r * 128 + (uint32_t)(((2 * s + aq_l) * 16) ^
                                                    ((r << 4) & 0x70));
                ldsm_x4(a[i], abase + off);
            }
            #pragma unroll
            for (int t = 0; t < 4; ++t) {
                int r = wn + t * 16 + brow_l;
                uint32_t off = r * 128 + (uint32_t)(((2 * s + bq_l) * 16) ^
                                                    ((r << 4) & 0x70));
                ldsm_x4(b[t], bbase + off);
            }
            #pragma unroll
            for (int i = 0; i < 4; ++i)
                #pragma unroll
                for (int j = 0; j < 8; ++j)
                    mma_tf32(d[i][j], a[i],
                             b[j >> 1][(j & 1) * 2], b[j >> 1][(j & 1) * 2 + 1]);
        }
    }

    // ---- epilogue: + bias, direct float2 stores ----
    const int g  = lane >> 2;
    const int c2 = (lane & 3) * 2;
    #pragma unroll
    for (int j = 0; j < 8; ++j) {
        const int col = n0 + wn + j * 8 + c2;
        const float2 bv = *reinterpret_cast<const float2*>(bias + col);
        #pragma unroll
        for (int i = 0; i < 4; ++i) {
            int r0 = m0 + wm + i * 16 + g;
            if (r0 < M) {
                float2 o = make_float2(d[i][j][0] + bv.x, d[i][j][1] + bv.y);
                *reinterpret_cast<float2*>(out + (size_t)r0 * E + col) = o;
            }
            int r1 = r0 + 8;
            if (r1 < M) {
                float2 o = make_float2(d[i][j][2] + bv.x, d[i][j][3] + bv.y);
                *reinterpret_cast<float2*>(out + (size_t)r1 * E + col) = o;
            }
        }
    }
}

} // namespace

extern "C" void kernel_launch(void* const* d_in, const int* in_sizes, int n_in,
                              void* d_out, int out_size) {
    const float* x     = (const float*)d_in[0];  // [96, 4, 420, 312]
    const float* Wm    = (const float*)d_in[1];  // [768, 672]
    const float* b     = (const float*)d_in[2];  // [768]
    const int*   valid = (const int*)  d_in[3];  // [390]
    float*       out   = (float*)d_out;          // [37440, 768]

    round_w<<<(E * K / 4 + 255) / 256, 256>>>(Wm);
    im2col<<<M, 256>>>(x, valid);

    cudaFuncSetAttribute(patch_embed_gemm,
                         cudaFuncAttributeMaxDynamicSharedMemorySize, SM_TOTAL);
    patch_embed_gemm<<<MBLK * NBLK, 128, SM_TOTAL>>>(b, out);
}

// round 9
// speedup vs baseline: 1.4625x; 1.4625x over previous
#include <cuda_runtime.h>
#include <cstdint>

// PatchEmbedding, 3-kernel plan:
//   1) round_w:  W -> tf32-rounded Wr (2 MB)
//   2) im2col:   x gather (float4) -> tf32-rounded Ar [37440,672] (100 MB)
//   3) gemm:     D = Ar * Wr^T + bias. cp.async 3-stage, mma.m16n8k8.tf32,
//                BM=256 x BN=128, 512 thr, 16 warps (4Mx4N), warp tile 64x32.

namespace {

constexpr int C_   = 4;
constexpr int Himg = 420;
constexpr int Wimg = 312;
constexpr int PH   = 14;
constexpr int PW   = 12;
constexpr int GW   = 26;
constexpr int E    = 768;
constexpr int NV   = 390;
constexpr int K    = 672;
constexpr int M    = 96 * NV;        // 37440
constexpr int HW_  = Himg * Wimg;
constexpr int CHW  = C_ * HW_;

constexpr int BM = 256, BN = 128, BK = 32;
constexpr int NKT    = K / BK;             // 21
constexpr int NBLK   = E / BN;             // 6
constexpr int MBLK   = (M + BM - 1) / BM;  // 147
constexpr int STAGES = 3;
constexpr int A_BYTES = BM * BK * 4;               // 32 KB
constexpr int STAGE_BYTES = (BM + BN) * BK * 4;    // 48 KB
constexpr int SM_TOTAL = STAGES * STAGE_BYTES;     // 144 KB

constexpr int K4 = K / 4;                 // 168 float4 per A row

} // namespace

// scratch (module-scope device globals; allocation-free at launch time)
__device__ float g_Ar[(size_t)M * K];   // ~100.6 MB, im2col'd + tf32-rounded
__device__ float g_Wr[(size_t)E * K];   // ~2 MB, tf32-rounded

namespace {

__device__ __forceinline__ uint32_t smem_u32(const void* p) {
    uint32_t a;
    asm("{ .reg .u64 t; cvta.to.shared.u64 t, %1; cvt.u32.u64 %0, t; }"
        : "=r"(a) : "l"(p));
    return a;
}

__device__ __forceinline__ uint32_t f2tf32(float v) {
    uint32_t r;
    asm("cvt.rna.tf32.f32 %0, %1;" : "=r"(r) : "f"(v));
    return r;
}

__device__ __forceinline__ void cp16(uint32_t dst, const float* src) {
    asm volatile("cp.async.cg.shared.global [%0], [%1], 16;"
                 :: "r"(dst), "l"(src) : "memory");
}

__device__ __forceinline__ void ldsm_x4(uint32_t r[4], uint32_t addr) {
    asm volatile("ldmatrix.sync.aligned.m8n8.x4.shared.b16 {%0,%1,%2,%3}, [%4];"
                 : "=r"(r[0]), "=r"(r[1]), "=r"(r[2]), "=r"(r[3]) : "r"(addr));
}

__device__ __forceinline__ void mma_tf32(float d[4], const uint32_t a[4],
                                         uint32_t b0, uint32_t b1) {
    asm volatile(
        "mma.sync.aligned.m16n8k8.row.col.f32.tf32.tf32.f32 "
        "{%0,%1,%2,%3}, {%4,%5,%6,%7}, {%8,%9}, {%0,%1,%2,%3};"
        : "+f"(d[0]), "+f"(d[1]), "+f"(d[2]), "+f"(d[3])
        : "r"(a[0]), "r"(a[1]), "r"(a[2]), "r"(a[3]), "r"(b0), "r"(b1));
}

// ---- pre-pass 1: round W to tf32 ----
__global__ void round_w(const float* __restrict__ Wm) {
    int i = blockIdx.x * blockDim.x + threadIdx.x;   // float4 index
    constexpr int N4 = E * K / 4;
    if (i < N4) {
        float4 v = reinterpret_cast<const float4*>(Wm)[i];
        v.x = __uint_as_float(f2tf32(v.x));
        v.y = __uint_as_float(f2tf32(v.y));
        v.z = __uint_as_float(f2tf32(v.z));
        v.w = __uint_as_float(f2tf32(v.w));
        reinterpret_cast<float4*>(g_Wr)[i] = v;
    }
}

// ---- pre-pass 2: im2col gather, float4 granularity (all 16B-aligned) ----
__global__ __launch_bounds__(256)
void im2col(const float* __restrict__ x, const int* __restrict__ valid) {
    int idx = blockIdx.x * blockDim.x + threadIdx.x;   // global float4 id
    if (idx >= M * K4) return;
    int m = idx / K4;
    int t = idx - m * K4;          // float4 within row: t = (c*14 + r)*3 + ch
    int c  = t / 42;               // 42 float4 per channel (14 rows x 3)
    int r3 = t - c * 42;
    int r  = r3 / 3;
    int ch = r3 - r * 3;

    int n  = m / NV;
    int v  = m - n * NV;
    int p  = __ldg(valid + v);
    int gi = p / GW;
    int gj = p - gi * GW;
    int base = n * CHW + gi * (PH * Wimg) + gj * PW;

    float4 val = *reinterpret_cast<const float4*>(
        x + base + c * HW_ + r * Wimg + ch * 4);
    val.x = __uint_as_float(f2tf32(val.x));
    val.y = __uint_as_float(f2tf32(val.y));
    val.z = __uint_as_float(f2tf32(val.z));
    val.w = __uint_as_float(f2tf32(val.w));
    reinterpret_cast<float4*>(g_Ar)[idx] = val;
}

// ---- main GEMM: 512 threads, 16 warps (4M x 4N), warp tile 64x32 ----
__global__ __launch_bounds__(512)
void patch_embed_gemm(const float* __restrict__ bias,
                      float*       __restrict__ out)
{
    extern __shared__ char smem[];
    const uint32_t sb = smem_u32(smem);

    const int tid  = threadIdx.x;
    const int lane = tid & 31;
    const int wid  = tid >> 5;

    const int bid = blockIdx.x;
    const int n0  = (bid % NBLK) * BN;   // n innermost -> A panel L2 reuse
    const int m0  = (bid / NBLK) * BM;

    // ---- cp.async assignments ----
    // A: thread -> (row tid>>1 of 256, half-row 64B), 4 x 16B chunks
    const int      ar_t  = tid >> 1;
    const int      acb   = (tid & 1) * 64;
    const uint32_t xma   = (ar_t << 4) & 0x70;
    const int      arow  = (m0 + ar_t < M) ? (m0 + ar_t) : (M - 1);
    const float*   asrc  = g_Ar + (size_t)arow * K + (tid & 1) * 16;
    // B: thread -> (row tid>>2 of 128, quarter-row 32B), 2 x 16B chunks
    const int      br_t  = tid >> 2;
    const int      bcb   = (tid & 3) * 32;
    const uint32_t xmb   = (br_t << 4) & 0x70;
    const float*   bsrc  = g_Wr + (size_t)(n0 + br_t) * K + (tid & 3) * 8;

    auto issue = [&](int kt) {
        const uint32_t st = sb + (kt % STAGES) * STAGE_BYTES;
        const float* as = asrc + kt * BK;
        const float* bs = bsrc + kt * BK;
        const uint32_t abase = st + ar_t * 128;
        #pragma unroll
        for (int j = 0; j < 4; ++j)
            cp16(abase + ((uint32_t)(acb + j * 16) ^ xma), as + j * 4);
        const uint32_t bbase = st + A_BYTES + br_t * 128;
        #pragma unroll
        for (int j = 0; j < 2; ++j)
            cp16(bbase + ((uint32_t)(bcb + j * 16) ^ xmb), bs + j * 4);
    };

    // ---- fragment assignment: wm in {0,64,128,192}, wn in {0,32,64,96} ----
    const int wm = (wid & 3) * 64;
    const int wn = (wid >> 2) * 32;
    const int arow_l = lane & 15;
    const int aq_l   = lane >> 4;
    const int brow_l = (lane & 7) + ((lane >> 4) << 3);
    const int bq_l   = (lane >> 3) & 1;

    float d[4][4][4];
    #pragma unroll
    for (int i = 0; i < 4; ++i)
        #pragma unroll
        for (int j = 0; j < 4; ++j)
            #pragma unroll
            for (int r = 0; r < 4; ++r)
                d[i][j][r] = 0.0f;

    issue(0);
    asm volatile("cp.async.commit_group;" ::: "memory");
    issue(1);
    asm volatile("cp.async.commit_group;" ::: "memory");

    for (int kt = 0; kt < NKT; ++kt) {
        asm volatile("cp.async.wait_group 1;" ::: "memory");
        __syncthreads();

        if (kt + 2 < NKT) issue(kt + 2);
        asm volatile("cp.async.commit_group;" ::: "memory");

        const uint32_t abase = sb + (kt % STAGES) * STAGE_BYTES;
        const uint32_t bbase = abase + A_BYTES;

        #pragma unroll
        for (int s = 0; s < 4; ++s) {
            uint32_t a[4][4];
            uint32_t b[2][4];
            #pragma unroll
            for (int i = 0; i < 4; ++i) {
                int r = wm + i * 16 + arow_l;
                uint32_t off = r * 128 + (uint32_t)(((2 * s + aq_l) * 16) ^
                                                    ((r << 4) & 0x70));
                ldsm_x4(a[i], abase + off);
            }
            #pragma unroll
            for (int t = 0; t < 2; ++t) {
                int r = wn + t * 16 + brow_l;
                uint32_t off = r * 128 + (uint32_t)(((2 * s + bq_l) * 16) ^
                                                    ((r << 4) & 0x70));
                ldsm_x4(b[t], bbase + off);
            }
            #pragma unroll
            for (int i = 0; i < 4; ++i)
                #pragma unroll
                for (int j = 0; j < 4; ++j)
                    mma_tf32(d[i][j], a[i],
                             b[j >> 1][(j & 1) * 2], b[j >> 1][(j & 1) * 2 + 1]);
        }
        __syncthreads();
    }

    // ---- epilogue: + bias, direct float2 stores ----
    const int g  = lane >> 2;
    const int c2 = (lane & 3) * 2;
    #pragma unroll
    for (int j = 0; j < 4; ++j) {
        const int col = n0 + wn + j * 8 + c2;
        const float2 bv = *reinterpret_cast<const float2*>(bias + col);
        #pragma unroll
        for (int i = 0; i < 4; ++i) {
            int r0 = m0 + wm + i * 16 + g;
            if (r0 < M) {
                float2 o = make_float2(d[i][j][0] + bv.x, d[i][j][1] + bv.y);
                *reinterpret_cast<float2*>(out + (size_t)r0 * E + col) = o;
            }
            int r1 = r0 + 8;
            if (r1 < M) {
                float2 o = make_float2(d[i][j][2] + bv.x, d[i][j][3] + bv.y);
                *reinterpret_cast<float2*>(out + (size_t)r1 * E + col) = o;
            }
        }
    }
}

} // namespace

extern "C" void kernel_launch(void* const* d_in, const int* in_sizes, int n_in,
                              void* d_out, int out_size) {
    const float* x     = (const float*)d_in[0];  // [96, 4, 420, 312]
    const float* Wm    = (const float*)d_in[1];  // [768, 672]
    const float* b     = (const float*)d_in[2];  // [768]
    const int*   valid = (const int*)  d_in[3];  // [390]
    float*       out   = (float*)d_out;          // [37440, 768]

    round_w<<<(E * K / 4 + 255) / 256, 256>>>(Wm);
    im2col<<<(M * K4 + 255) / 256, 256>>>(x, valid);

    cudaFuncSetAttribute(patch_embed_gemm,
                         cudaFuncAttributeMaxDynamicSharedMemorySize, SM_TOTAL);
    patch_embed_gemm<<<MBLK * NBLK, 512, SM_TOTAL>>>(b, out);
}

// round 10
// speedup vs baseline: 2.1012x; 1.4367x over previous
#include <cuda_runtime.h>
#include <cuda_fp16.h>
#include <cstdint>

// PatchEmbedding, 3-kernel plan (fp16 tensor path):
//   1) round_wh: W -> fp16 Wh [768, 704] (K padded 672->704 with zeros)
//   2) im2col:   x gather -> fp16 Ah [37440, 704] (~53 MB)
//   3) gemm:     D = Ah * Wh^T + bias (fp32 accum). cp.async 3-stage,
//                mma.m16n8k16.f16, BM=256 x BN=128, 512 thr, warp tile 64x32.
// fp16 and tf32 have identical 11-bit significands -> same rel_err (~2.9e-4),
// but k16 halves the tensor instruction count vs tf32 k8.

namespace {

constexpr int C_   = 4;
constexpr int Himg = 420;
constexpr int Wimg = 312;
constexpr int PH   = 14;
constexpr int PW   = 12;
constexpr int GW   = 26;
constexpr int E    = 768;
constexpr int NV   = 390;
constexpr int K    = 672;
constexpr int Kp   = 704;            // padded K (multiple of 64)
constexpr int Kp4  = Kp / 4;         // 176 half4-groups per row
constexpr int M    = 96 * NV;        // 37440
constexpr int HW_  = Himg * Wimg;
constexpr int CHW  = C_ * HW_;

constexpr int BM = 256, BN = 128, BK = 64;   // BK in fp16 elements (128 B)
constexpr int NKT    = Kp / BK;              // 11
constexpr int NBLK   = E / BN;               // 6
constexpr int MBLK   = (M + BM - 1) / BM;    // 147
constexpr int STAGES = 3;
constexpr int A_BYTES = BM * BK * 2;               // 32 KB
constexpr int STAGE_BYTES = (BM + BN) * BK * 2;    // 48 KB
constexpr int SM_TOTAL = STAGES * STAGE_BYTES;     // 144 KB

} // namespace

// scratch (module-scope device globals; allocation-free at launch time)
__device__ __align__(16) __half g_Ah[(size_t)M * Kp];   // ~52.7 MB
__device__ __align__(16) __half g_Wh[(size_t)E * Kp];   // ~1.1 MB

namespace {

__device__ __forceinline__ uint32_t smem_u32(const void* p) {
    uint32_t a;
    asm("{ .reg .u64 t; cvta.to.shared.u64 t, %1; cvt.u32.u64 %0, t; }"
        : "=r"(a) : "l"(p));
    return a;
}

__device__ __forceinline__ void cp16(uint32_t dst, const void* src) {
    asm volatile("cp.async.cg.shared.global [%0], [%1], 16;"
                 :: "r"(dst), "l"(src) : "memory");
}

__device__ __forceinline__ void ldsm_x4(uint32_t r[4], uint32_t addr) {
    asm volatile("ldmatrix.sync.aligned.m8n8.x4.shared.b16 {%0,%1,%2,%3}, [%4];"
                 : "=r"(r[0]), "=r"(r[1]), "=r"(r[2]), "=r"(r[3]) : "r"(addr));
}

__device__ __forceinline__ void mma_f16(float d[4], const uint32_t a[4],
                                        uint32_t b0, uint32_t b1) {
    asm volatile(
        "mma.sync.aligned.m16n8k16.row.col.f32.f16.f16.f32 "
        "{%0,%1,%2,%3}, {%4,%5,%6,%7}, {%8,%9}, {%0,%1,%2,%3};"
        : "+f"(d[0]), "+f"(d[1]), "+f"(d[2]), "+f"(d[3])
        : "r"(a[0]), "r"(a[1]), "r"(a[2]), "r"(a[3]), "r"(b0), "r"(b1));
}

__device__ __forceinline__ uint2 pack4(float4 v) {
    __half2 lo = __floats2half2_rn(v.x, v.y);
    __half2 hi = __floats2half2_rn(v.z, v.w);
    uint2 r;
    r.x = *reinterpret_cast<uint32_t*>(&lo);
    r.y = *reinterpret_cast<uint32_t*>(&hi);
    return r;
}

// ---- pre-pass 1: W -> fp16, padded to Kp ----
__global__ void round_wh(const float* __restrict__ Wm) {
    int idx = blockIdx.x * blockDim.x + threadIdx.x;   // half4-group id
    if (idx >= E * Kp4) return;
    int e = idx / Kp4;
    int t = idx - e * Kp4;
    uint2 val = make_uint2(0, 0);
    if (t < K / 4)
        val = pack4(*reinterpret_cast<const float4*>(Wm + (size_t)e * K + t * 4));
    *reinterpret_cast<uint2*>(g_Wh + (size_t)e * Kp + t * 4) = val;
}

// ---- pre-pass 2: im2col gather -> fp16, padded to Kp ----
__global__ __launch_bounds__(256)
void im2col(const float* __restrict__ x, const int* __restrict__ valid) {
    int idx = blockIdx.x * blockDim.x + threadIdx.x;   // half4-group id
    if (idx >= M * Kp4) return;
    int m = idx / Kp4;
    int t = idx - m * Kp4;           // group within row

    uint2 val = make_uint2(0, 0);
    if (t < K / 4) {
        int c  = t / 42;             // 42 float4 per channel (14 rows x 3)
        int r3 = t - c * 42;
        int r  = r3 / 3;
        int ch = r3 - r * 3;

        int n  = m / NV;
        int v  = m - n * NV;
        int p  = __ldg(valid + v);
        int gi = p / GW;
        int gj = p - gi * GW;
        int base = n * CHW + gi * (PH * Wimg) + gj * PW;

        val = pack4(*reinterpret_cast<const float4*>(
            x + base + c * HW_ + r * Wimg + ch * 4));
    }
    *reinterpret_cast<uint2*>(g_Ah + (size_t)m * Kp + t * 4) = val;
}

// ---- main GEMM: 512 threads, 16 warps (4M x 4N), warp tile 64x32, fp16 ----
__global__ __launch_bounds__(512)
void patch_embed_gemm(const float* __restrict__ bias,
                      float*       __restrict__ out)
{
    extern __shared__ char smem[];
    const uint32_t sb = smem_u32(smem);

    const int tid  = threadIdx.x;
    const int lane = tid & 31;
    const int wid  = tid >> 5;

    const int bid = blockIdx.x;
    const int n0  = (bid % NBLK) * BN;   // n innermost -> A panel L2 reuse
    const int m0  = (bid / NBLK) * BM;

    // ---- cp.async assignments (rows are 128 B = 64 halves) ----
    // A: thread -> (row tid>>1 of 256, half-row 64B), 4 x 16B chunks
    const int      ar_t = tid >> 1;
    const int      acb  = (tid & 1) * 64;               // byte col base
    const uint32_t xma  = (ar_t << 4) & 0x70;
    const int      arow = (m0 + ar_t < M) ? (m0 + ar_t) : (M - 1);
    const __half*  asrc = g_Ah + (size_t)arow * Kp + (tid & 1) * 32;
    // B: thread -> (row tid>>2 of 128, quarter-row 32B), 2 x 16B chunks
    const int      br_t = tid >> 2;
    const int      bcb  = (tid & 3) * 32;
    const uint32_t xmb  = (br_t << 4) & 0x70;
    const __half*  bsrc = g_Wh + (size_t)(n0 + br_t) * Kp + (tid & 3) * 16;

    auto issue = [&](int kt) {
        const uint32_t st = sb + (kt % STAGES) * STAGE_BYTES;
        const __half* as = asrc + kt * BK;
        const __half* bs = bsrc + kt * BK;
        const uint32_t abase = st + ar_t * 128;
        #pragma unroll
        for (int j = 0; j < 4; ++j)
            cp16(abase + ((uint32_t)(acb + j * 16) ^ xma), as + j * 8);
        const uint32_t bbase = st + A_BYTES + br_t * 128;
        #pragma unroll
        for (int j = 0; j < 2; ++j)
            cp16(bbase + ((uint32_t)(bcb + j * 16) ^ xmb), bs + j * 8);
    };

    // ---- fragment assignment: wm in {0,64,128,192}, wn in {0,32,64,96} ----
    const int wm = (wid & 3) * 64;
    const int wn = (wid >> 2) * 32;
    const int row_l = lane & 15;        // ldmatrix row within 16-row group
    const int q_l   = lane >> 4;        // 16B column selector

    float d[4][4][4];
    #pragma unroll
    for (int i = 0; i < 4; ++i)
        #pragma unroll
        for (int j = 0; j < 4; ++j)
            #pragma unroll
            for (int r = 0; r < 4; ++r)
                d[i][j][r] = 0.0f;

    issue(0);
    asm volatile("cp.async.commit_group;" ::: "memory");
    issue(1);
    asm volatile("cp.async.commit_group;" ::: "memory");

    for (int kt = 0; kt < NKT; ++kt) {
        asm volatile("cp.async.wait_group 1;" ::: "memory");
        __syncthreads();

        if (kt + 2 < NKT) issue(kt + 2);
        asm volatile("cp.async.commit_group;" ::: "memory");

        const uint32_t abase = sb + (kt % STAGES) * STAGE_BYTES;
        const uint32_t bbase = abase + A_BYTES;

        #pragma unroll
        for (int s = 0; s < 4; ++s) {          // 4 k16 steps per 64-k tile
            uint32_t a[4][4];                  // a[i] = {a0,a1,a2,a3}
            uint32_t b[2][4];                  // b[t] = n16 group .x4
            #pragma unroll
            for (int i = 0; i < 4; ++i) {
                int r = wm + i * 16 + row_l;
                uint32_t off = r * 128 + (uint32_t)((s * 32 + q_l * 16) ^
                                                    ((r << 4) & 0x70));
                ldsm_x4(a[i], abase + off);
            }
            #pragma unroll
            for (int t = 0; t < 2; ++t) {
                int r = wn + t * 16 + row_l;
                uint32_t off = r * 128 + (uint32_t)((s * 32 + q_l * 16) ^
                                                    ((r << 4) & 0x70));
                ldsm_x4(b[t], bbase + off);
            }
            // b[t]: r0=(n0-7,k0-7) r1=(n8-15,k0-7) r2=(n0-7,k8-15) r3=(n8-15,k8-15)
            #pragma unroll
            for (int i = 0; i < 4; ++i)
                #pragma unroll
                for (int j = 0; j < 4; ++j)
                    mma_f16(d[i][j], a[i],
                            b[j >> 1][j & 1], b[j >> 1][(j & 1) + 2]);
        }
        __syncthreads();
    }

    // ---- epilogue: + bias, direct float2 stores ----
    const int g  = lane >> 2;
    const int c2 = (lane & 3) * 2;
    #pragma unroll
    for (int j = 0; j < 4; ++j) {
        const int col = n0 + wn + j * 8 + c2;
        const float2 bv = *reinterpret_cast<const float2*>(bias + col);
        #pragma unroll
        for (int i = 0; i < 4; ++i) {
            int r0 = m0 + wm + i * 16 + g;
            if (r0 < M) {
                float2 o = make_float2(d[i][j][0] + bv.x, d[i][j][1] + bv.y);
                *reinterpret_cast<float2*>(out + (size_t)r0 * E + col) = o;
            }
            int r1 = r0 + 8;
            if (r1 < M) {
                float2 o = make_float2(d[i][j][2] + bv.x, d[i][j][3] + bv.y);
                *reinterpret_cast<float2*>(out + (size_t)r1 * E + col) = o;
            }
        }
    }
}

} // namespace

extern "C" void kernel_launch(void* const* d_in, const int* in_sizes, int n_in,
                              void* d_out, int out_size) {
    const float* x     = (const float*)d_in[0];  // [96, 4, 420, 312]
    const float* Wm    = (const float*)d_in[1];  // [768, 672]
    const float* b     = (const float*)d_in[2];  // [768]
    const int*   valid = (const int*)  d_in[3];  // [390]
    float*       out   = (float*)d_out;          // [37440, 768]

    round_wh<<<(E * Kp4 + 255) / 256, 256>>>(Wm);
    im2col<<<(M * Kp4 + 255) / 256, 256>>>(x, valid);

    cudaFuncSetAttribute(patch_embed_gemm,
                         cudaFuncAttributeMaxDynamicSharedMemorySize, SM_TOTAL);
    patch_embed_gemm<<<MBLK * NBLK, 512, SM_TOTAL>>>(b, out);
}

// round 11
// speedup vs baseline: 2.1877x; 1.0412x over previous
#include <cuda_runtime.h>
#include <cuda_fp16.h>
#include <cstdint>

// PatchEmbedding, fp16 tensor path, 2 kernels:
//   1) prep: W -> fp16 Wh [768,704] AND im2col x -> fp16 Ah [37440,704]
//   2) gemm: D = Ah * Wh^T + bias (fp32 accum). cp.async 3-stage,
//      mma.m16n8k16.f16, BM=256 x BN=128, 512 thr, warp tile 64x32,
//      fragment double-buffering across k16 steps, single sync per k-iter.

namespace {

constexpr int C_   = 4;
constexpr int Himg = 420;
constexpr int Wimg = 312;
constexpr int PH   = 14;
constexpr int PW   = 12;
constexpr int GW   = 26;
constexpr int E    = 768;
constexpr int NV   = 390;
constexpr int K    = 672;
constexpr int Kp   = 704;            // padded K (multiple of 64)
constexpr int Kp4  = Kp / 4;         // 176 half4-groups per row
constexpr int M    = 96 * NV;        // 37440
constexpr int HW_  = Himg * Wimg;
constexpr int CHW  = C_ * HW_;

constexpr int BM = 256, BN = 128, BK = 64;   // BK in fp16 elements (128 B)
constexpr int NKT    = Kp / BK;              // 11
constexpr int NBLK   = E / BN;               // 6
constexpr int MBLK   = (M + BM - 1) / BM;    // 147
constexpr int STAGES = 3;
constexpr int A_BYTES = BM * BK * 2;               // 32 KB
constexpr int STAGE_BYTES = (BM + BN) * BK * 2;    // 48 KB
constexpr int SM_TOTAL = STAGES * STAGE_BYTES;     // 144 KB

constexpr int NW4 = E * Kp4;         // W half4-groups
constexpr int NA4 = M * Kp4;         // A half4-groups

} // namespace

// scratch (module-scope device globals; allocation-free at launch time)
__device__ __align__(16) __half g_Ah[(size_t)M * Kp];   // ~52.7 MB
__device__ __align__(16) __half g_Wh[(size_t)E * Kp];   // ~1.1 MB

namespace {

__device__ __forceinline__ uint32_t smem_u32(const void* p) {
    uint32_t a;
    asm("{ .reg .u64 t; cvta.to.shared.u64 t, %1; cvt.u32.u64 %0, t; }"
        : "=r"(a) : "l"(p));
    return a;
}

__device__ __forceinline__ void cp16(uint32_t dst, const void* src) {
    asm volatile("cp.async.cg.shared.global [%0], [%1], 16;"
                 :: "r"(dst), "l"(src) : "memory");
}

__device__ __forceinline__ void ldsm_x4(uint32_t r[4], uint32_t addr) {
    asm volatile("ldmatrix.sync.aligned.m8n8.x4.shared.b16 {%0,%1,%2,%3}, [%4];"
                 : "=r"(r[0]), "=r"(r[1]), "=r"(r[2]), "=r"(r[3]) : "r"(addr));
}

__device__ __forceinline__ void mma_f16(float d[4], const uint32_t a[4],
                                        uint32_t b0, uint32_t b1) {
    asm volatile(
        "mma.sync.aligned.m16n8k16.row.col.f32.f16.f16.f32 "
        "{%0,%1,%2,%3}, {%4,%5,%6,%7}, {%8,%9}, {%0,%1,%2,%3};"
        : "+f"(d[0]), "+f"(d[1]), "+f"(d[2]), "+f"(d[3])
        : "r"(a[0]), "r"(a[1]), "r"(a[2]), "r"(a[3]), "r"(b0), "r"(b1));
}

__device__ __forceinline__ uint2 pack4(float4 v) {
    __half2 lo = __floats2half2_rn(v.x, v.y);
    __half2 hi = __floats2half2_rn(v.z, v.w);
    uint2 r;
    r.x = *reinterpret_cast<uint32_t*>(&lo);
    r.y = *reinterpret_cast<uint32_t*>(&hi);
    return r;
}

// ---- merged pre-pass: W -> fp16 (padded) then A im2col -> fp16 (padded) ----
__global__ __launch_bounds__(256)
void prep(const float* __restrict__ x, const float* __restrict__ Wm,
          const int* __restrict__ valid) {
    int idx = blockIdx.x * blockDim.x + threadIdx.x;
    if (idx < NW4) {
        int e = idx / Kp4;
        int t = idx - e * Kp4;
        uint2 val = make_uint2(0, 0);
        if (t < K / 4)
            val = pack4(*reinterpret_cast<const float4*>(Wm + (size_t)e * K + t * 4));
        *reinterpret_cast<uint2*>(g_Wh + (size_t)e * Kp + t * 4) = val;
        return;
    }
    idx -= NW4;
    if (idx >= NA4) return;
    int m = idx / Kp4;
    int t = idx - m * Kp4;
    uint2 val = make_uint2(0, 0);
    if (t < K / 4) {
        int c  = t / 42;             // 42 float4 per channel (14 rows x 3)
        int r3 = t - c * 42;
        int r  = r3 / 3;
        int ch = r3 - r * 3;
        int n  = m / NV;
        int v  = m - n * NV;
        int p  = __ldg(valid + v);
        int gi = p / GW;
        int gj = p - gi * GW;
        int base = n * CHW + gi * (PH * Wimg) + gj * PW;
        val = pack4(*reinterpret_cast<const float4*>(
            x + base + c * HW_ + r * Wimg + ch * 4));
    }
    *reinterpret_cast<uint2*>(g_Ah + (size_t)m * Kp + t * 4) = val;
}

// ---- main GEMM ----
__global__ __launch_bounds__(512)
void patch_embed_gemm(const float* __restrict__ bias,
                      float*       __restrict__ out)
{
    extern __shared__ char smem[];
    const uint32_t sb = smem_u32(smem);

    const int tid  = threadIdx.x;
    const int lane = tid & 31;
    const int wid  = tid >> 5;

    const int bid = blockIdx.x;
    const int n0  = (bid % NBLK) * BN;   // n innermost -> A panel L2 reuse
    const int m0  = (bid / NBLK) * BM;

    // ---- cp.async assignments (rows are 128 B = 64 halves) ----
    const int      ar_t = tid >> 1;
    const int      acb  = (tid & 1) * 64;
    const uint32_t xma  = (ar_t << 4) & 0x70;
    const int      arow = (m0 + ar_t < M) ? (m0 + ar_t) : (M - 1);
    const __half*  asrc = g_Ah + (size_t)arow * Kp + (tid & 1) * 32;
    const int      br_t = tid >> 2;
    const int      bcb  = (tid & 3) * 32;
    const uint32_t xmb  = (br_t << 4) & 0x70;
    const __half*  bsrc = g_Wh + (size_t)(n0 + br_t) * Kp + (tid & 3) * 16;

    auto issue = [&](int kt) {
        const uint32_t st = sb + (kt % STAGES) * STAGE_BYTES;
        const __half* as = asrc + kt * BK;
        const __half* bs = bsrc + kt * BK;
        const uint32_t abase = st + ar_t * 128;
        #pragma unroll
        for (int j = 0; j < 4; ++j)
            cp16(abase + ((uint32_t)(acb + j * 16) ^ xma), as + j * 8);
        const uint32_t bbase = st + A_BYTES + br_t * 128;
        #pragma unroll
        for (int j = 0; j < 2; ++j)
            cp16(bbase + ((uint32_t)(bcb + j * 16) ^ xmb), bs + j * 8);
    };

    // ---- fragment addressing (lean): mask constant under row+16 ----
    const int wm = (wid & 3) * 64;
    const int wn = (wid >> 2) * 32;
    const int row_l = lane & 15;
    const int q_l   = lane >> 4;
    const uint32_t mask_a = (uint32_t)(((wm + row_l) << 4) & 0x70);
    const uint32_t mask_b = (uint32_t)(((wn + row_l) << 4) & 0x70);
    const uint32_t abase_t = (uint32_t)((wm + row_l) * 128);   // + stage base
    const uint32_t bbase_t = (uint32_t)((wn + row_l) * 128);

    float d[4][4][4];
    #pragma unroll
    for (int i = 0; i < 4; ++i)
        #pragma unroll
        for (int j = 0; j < 4; ++j)
            #pragma unroll
            for (int r = 0; r < 4; ++r)
                d[i][j][r] = 0.0f;

    issue(0);
    asm volatile("cp.async.commit_group;" ::: "memory");
    issue(1);
    asm volatile("cp.async.commit_group;" ::: "memory");

    uint32_t a[2][4][4];     // [buf][i][frag]
    uint32_t b[2][2][4];     // [buf][t][frag]

    for (int kt = 0; kt < NKT; ++kt) {
        asm volatile("cp.async.wait_group 1;" ::: "memory");
        __syncthreads();

        if (kt + 2 < NKT) issue(kt + 2);
        asm volatile("cp.async.commit_group;" ::: "memory");

        const uint32_t astg = sb + (kt % STAGES) * STAGE_BYTES + abase_t;
        const uint32_t bstg = sb + (kt % STAGES) * STAGE_BYTES + A_BYTES + bbase_t;

        // preload s = 0 fragments
        {
            const uint32_t ca = (uint32_t)(q_l * 16) ^ mask_a;
            const uint32_t cb = (uint32_t)(q_l * 16) ^ mask_b;
            #pragma unroll
            for (int i = 0; i < 4; ++i) ldsm_x4(a[0][i], astg + i * 2048 + ca);
            #pragma unroll
            for (int t = 0; t < 2; ++t) ldsm_x4(b[0][t], bstg + t * 2048 + cb);
        }

        #pragma unroll
        for (int s = 0; s < 4; ++s) {
            const int cur = s & 1, nxt = cur ^ 1;
            if (s < 3) {       // prefetch s+1 fragments under this step's MMAs
                const uint32_t ca = (uint32_t)((s + 1) * 32 + q_l * 16) ^ mask_a;
                const uint32_t cb = (uint32_t)((s + 1) * 32 + q_l * 16) ^ mask_b;
                #pragma unroll
                for (int i = 0; i < 4; ++i) ldsm_x4(a[nxt][i], astg + i * 2048 + ca);
                #pragma unroll
                for (int t = 0; t < 2; ++t) ldsm_x4(b[nxt][t], bstg + t * 2048 + cb);
            }
            #pragma unroll
            for (int i = 0; i < 4; ++i)
                #pragma unroll
                for (int j = 0; j < 4; ++j)
                    mma_f16(d[i][j], a[cur][i],
                            b[cur][j >> 1][j & 1], b[cur][j >> 1][(j & 1) + 2]);
        }
        // no bottom sync: top-of-next-iter sync orders reuse of stage kt%3
    }

    // ---- epilogue: + bias, direct float2 stores ----
    const int g  = lane >> 2;
    const int c2 = (lane & 3) * 2;
    #pragma unroll
    for (int j = 0; j < 4; ++j) {
        const int col = n0 + wn + j * 8 + c2;
        const float2 bv = *reinterpret_cast<const float2*>(bias + col);
        #pragma unroll
        for (int i = 0; i < 4; ++i) {
            int r0 = m0 + wm + i * 16 + g;
            if (r0 < M) {
                float2 o = make_float2(d[i][j][0] + bv.x, d[i][j][1] + bv.y);
                *reinterpret_cast<float2*>(out + (size_t)r0 * E + col) = o;
            }
            int r1 = r0 + 8;
            if (r1 < M) {
                float2 o = make_float2(d[i][j][2] + bv.x, d[i][j][3] + bv.y);
                *reinterpret_cast<float2*>(out + (size_t)r1 * E + col) = o;
            }
        }
    }
}

} // namespace

extern "C" void kernel_launch(void* const* d_in, const int* in_sizes, int n_in,
                              void* d_out, int out_size) {
    const float* x     = (const float*)d_in[0];  // [96, 4, 420, 312]
    const float* Wm    = (const float*)d_in[1];  // [768, 672]
    const float* b     = (const float*)d_in[2];  // [768]
    const int*   valid = (const int*)  d_in[3];  // [390]
    float*       out   = (float*)d_out;          // [37440, 768]

    prep<<<(NW4 + NA4 + 255) / 256, 256>>>(x, Wm, valid);

    cudaFuncSetAttribute(patch_embed_gemm,
                         cudaFuncAttributeMaxDynamicSharedMemorySize, SM_TOTAL);
    patch_embed_gemm<<<MBLK * NBLK, 512, SM_TOTAL>>>(b, out);
}